// round 13
// baseline (speedup 1.0000x reference)
#include <cuda_runtime.h>
#include <cuda_bf16.h>

#define IMG_H 384
#define IMG_W 640
#define N_PLANES 96            // 32 * 3
#define WIN 11
#define HALO 5
#define OUT_W_TILE 246
#define NX 3                   // 246 + 246 + 148 = 640
#define NY 1
#define ROWS_PER_BLK (IMG_H / NY)       // 384
#define CHUNK 16
#define NCHUNKS (ROWS_PER_BLK / CHUNK)  // 24
#define NTHREADS 256

// SMEM layout (float units):
//   A01: CHUNK rows of VS2 float2 pairs (Sp, St)    -- packed
//   A23: CHUNK rows of VS1 floats      (Spp + Stt)
//   A4 : CHUNK rows of VS1 floats      (Spt)
// VS2=258: 2*VS2 = 516 == 4 (mod 32)  -> conflict-free 8-lane LDS.128 phases
// VS1=260: VS1 == 4 (mod 32)          -> conflict-free 8-lane LDS.128 phases
#define VS2 258
#define VS1 260
#define A01_OFF 0
#define A23_OFF (CHUNK * VS2 * 2)            // 8256
#define A4_OFF  (A23_OFF + CHUNK * VS1)      // 12416
#define SMEM_FLOATS (A4_OFF + CHUNK * VS1 + 64)  // 16640 (incl. overread pad)
#define SMEM_BYTES (SMEM_FLOATS * 4)             // 66560 B

#define C1F 1e-4f
#define C2F 9e-4f
#define N_BLOCKS (NX * NY * N_PLANES)  // 288

__device__ float g_partials[N_BLOCKS];
__device__ unsigned int g_count = 0;

// ---- packed f32x2 helpers (Blackwell FFMA2 path) ----
__device__ __forceinline__ unsigned long long pk2(float lo, float hi) {
    unsigned long long r;
    asm("mov.b64 %0, {%1, %2};" : "=l"(r) : "f"(lo), "f"(hi));
    return r;
}
__device__ __forceinline__ void upk2(unsigned long long v, float& lo, float& hi) {
    asm("mov.b64 {%0, %1}, %2;" : "=f"(lo), "=f"(hi) : "l"(v));
}
__device__ __forceinline__ unsigned long long add2(unsigned long long a, unsigned long long b) {
    unsigned long long r;
    asm("add.rn.f32x2 %0, %1, %2;" : "=l"(r) : "l"(a), "l"(b));
    return r;
}
__device__ __forceinline__ unsigned long long fma2(unsigned long long a, unsigned long long b,
                                                   unsigned long long c) {
    unsigned long long r;
    asm("fma.rn.f32x2 %0, %1, %2, %3;" : "=l"(r) : "l"(a), "l"(b), "l"(c));
    return r;
}
#define NEG1_X2 0xBF800000BF800000ULL   // packed (-1.0f, -1.0f)

__global__ __launch_bounds__(NTHREADS, 2)
void ssim_main(const float* __restrict__ pred, const float* __restrict__ targ,
               float* __restrict__ out) {
    extern __shared__ float smem[];

    const int b = blockIdx.x;
    const int xt = b % NX;
    const int plane = b / NX;

    const int x0 = xt * OUT_W_TILE;
    const int outw = min(OUT_W_TILE, IMG_W - x0);   // 246 or 148
    const int inw = outw + 2 * HALO;
    const int r0 = 0;

    const size_t poff = (size_t)plane * (IMG_H * IMG_W);
    const float* __restrict__ P = pred + poff;
    const float* __restrict__ T = targ + poff;

    // ---------- vertical-pass identity ----------
    const int c = threadIdx.x;               // buffer column
    const int gx = x0 - HALO + c;            // global column
    const bool cvalid = (c < inw);
    const bool colin = cvalid && (gx >= 0) && (gx < IMG_W);

    unsigned long long vs01 = 0ULL;          // packed (sum p, sum t)
    float vs23 = 0.f;                        // sum (p*p + t*t)
    float vs4 = 0.f;                         // sum (p*t)

    // 10-deep register shift-register of packed (p,t) input rows.
    unsigned long long hist[10];

    // warmup: rows -5 .. 4
    #pragma unroll
    for (int k = 0; k < 10; ++k) {
        const int rr = r0 - HALO + k;
        float p = 0.f, t = 0.f;
        if (colin && rr >= 0) {              // rr < IMG_H always in warmup
            p = P[rr * IMG_W + gx];
            t = T[rr * IMG_W + gx];
        }
        hist[k] = pk2(p, t);
        vs01 = add2(vs01, pk2(p, t));
        vs23 = fmaf(p, p, fmaf(t, t, vs23));
        vs4  = fmaf(p, t, vs4);
    }

    // ---------- horizontal-pass identity ----------
    const int hrow = threadIdx.x & (CHUNK - 1);   // 0..15
    const int hseg = threadIdx.x >> 4;            // 0..15
    const int xs = hseg * 16;
    const bool segvalid = (xs < outw);
    const int nvalid = segvalid ? min(16, outw - xs) : 0;

    float acc = 0.f;
    const float KK  = 1.0f / 121.0f;
    const float K2C = KK * KK;
    const float TK2 = 2.0f * K2C;
    const float C12 = C1F + C2F;

    for (int ch = 0; ch < NCHUNKS; ++ch) {
        const int rbase = r0 + ch * CHUNK;

        // ===== vertical pass: delta-form, 1 op/row on each carried chain =====
        #pragma unroll
        for (int i = 0; i < CHUNK; ++i) {
            // incoming row r+5
            const int rr = rbase + i + HALO;
            float p = 0.f, t = 0.f;
            if (colin && rr < IMG_H) {
                p = P[rr * IMG_W + gx];
                t = T[rr * IMG_W + gx];
            }
            const unsigned long long nw = pk2(p, t);
            float po, to; upk2(hist[0], po, to);

            // store values: old carried sum + incoming (off loop-carried chain)
            if (cvalid) {
                *reinterpret_cast<unsigned long long*>(
                    &smem[A01_OFF + (i * VS2 + c) * 2]) = add2(vs01, nw);
                smem[A23_OFF + i * VS1 + c] = fmaf(p, p, fmaf(t, t, vs23));
                smem[A4_OFF  + i * VS1 + c] = fmaf(p, t, vs4);
            }

            // carried updates: vs += (incoming - outgoing), deltas off-chain
            vs01 = add2(vs01, fma2(hist[0], NEG1_X2, nw));
            vs23 += fmaf(p, p, t * t) - fmaf(po, po, to * to);
            vs4  += fmaf(p, t, -(po * to));

            #pragma unroll
            for (int k = 0; k < 9; ++k) hist[k] = hist[k + 1];
            hist[9] = nw;
        }
        __syncthreads();

        // ===== horizontal pass: vectorized register-window sliding sums =====
        if (segvalid) {
            float numA[16], denF[16];

            // Pass A: packed (Sp, St) -> numA = 2k^2*ab + C1, denA = k^2*(a^2+b^2) + C1
            {
                const ulonglong2* b01 =
                    reinterpret_cast<const ulonglong2*>(smem) + ((hrow * VS2 + xs) >> 1);
                unsigned long long v[28];
                #pragma unroll
                for (int k = 0; k < 14; ++k) {
                    ulonglong2 u = b01[k];          // LDS.128, conflict-free
                    v[2 * k] = u.x; v[2 * k + 1] = u.y;
                }
                // tree sum of v[0..10]
                unsigned long long t01 = add2(v[0], v[1]);
                unsigned long long t23 = add2(v[2], v[3]);
                unsigned long long t45 = add2(v[4], v[5]);
                unsigned long long t67 = add2(v[6], v[7]);
                unsigned long long t89 = add2(v[8], v[9]);
                unsigned long long S = add2(add2(add2(t01, t23), add2(t45, t67)),
                                            add2(t89, v[10]));
                #pragma unroll
                for (int j = 0; j < 16; ++j) {
                    float a, bb; upk2(S, a, bb);
                    float ab = a * bb;
                    float V  = fmaf(a, a, bb * bb);
                    numA[j] = fmaf(TK2, ab, C1F);
                    denF[j] = fmaf(K2C, V, C1F);    // den1 (for now)
                    if (j < 15)                      // fused diff: 1 op on chain
                        S = add2(S, fma2(v[j], NEG1_X2, v[j + WIN]));
                }
            }
            // Pass B: S = box sum of (pp+tt); den2 = k*S - den1 + (C1+C2); denF = den1*den2
            {
                const float4* b23 =
                    reinterpret_cast<const float4*>(&smem[A23_OFF + hrow * VS1 + xs]);
                float w[28];
                #pragma unroll
                for (int k = 0; k < 7; ++k) {
                    float4 u = b23[k];
                    w[4*k] = u.x; w[4*k+1] = u.y; w[4*k+2] = u.z; w[4*k+3] = u.w;
                }
                float t01 = w[0] + w[1], t23 = w[2] + w[3];
                float t45 = w[4] + w[5], t67 = w[6] + w[7];
                float t89 = w[8] + w[9];
                float S = ((t01 + t23) + (t45 + t67)) + (t89 + w[10]);
                #pragma unroll
                for (int j = 0; j < 16; ++j) {
                    float den1 = denF[j];
                    float den2 = fmaf(KK, S, C12 - den1);
                    denF[j] = den1 * den2;
                    if (j < 15) {
                        float d = w[j + WIN] - w[j];   // off-chain diff
                        S += d;
                    }
                }
            }
            // Pass C: S = box sum of pt; num2 = 2k*S + C12 - n1;
            // quad fraction combining -> one divide per 4 pixels.
            {
                const float4* b4 =
                    reinterpret_cast<const float4*>(&smem[A4_OFF + hrow * VS1 + xs]);
                float w[28];
                #pragma unroll
                for (int k = 0; k < 7; ++k) {
                    float4 u = b4[k];
                    w[4*k] = u.x; w[4*k+1] = u.y; w[4*k+2] = u.z; w[4*k+3] = u.w;
                }
                float t01 = w[0] + w[1], t23 = w[2] + w[3];
                float t45 = w[4] + w[5], t67 = w[6] + w[7];
                float t89 = w[8] + w[9];
                float S = ((t01 + t23) + (t45 + t67)) + (t89 + w[10]);
                #pragma unroll
                for (int q = 0; q < 4; ++q) {
                    float Nacc, Dacc;
                    #pragma unroll
                    for (int u = 0; u < 4; ++u) {
                        const int j = q * 4 + u;
                        float n1 = numA[j];
                        float n2 = fmaf(2.0f * KK, S, C12 - n1);
                        float Nj = (j < nvalid) ? n1 * n2 : 0.f;
                        float Dj = (j < nvalid) ? denF[j] : 1.0f;
                        if (u == 0) { Nacc = Nj; Dacc = Dj; }
                        else {
                            Nacc = fmaf(Nacc, Dj, Nj * Dacc);
                            Dacc = Dacc * Dj;
                        }
                        if (j < 15) {
                            float d = w[j + WIN] - w[j];   // off-chain diff
                            S += d;
                        }
                    }
                    acc += __fdividef(Nacc, Dacc);
                }
            }
        }
        __syncthreads();
    }

    // ---------- deterministic block reduction ----------
    smem[threadIdx.x] = acc;
    __syncthreads();
    #pragma unroll
    for (int off = NTHREADS / 2; off > 0; off >>= 1) {
        if (threadIdx.x < off) smem[threadIdx.x] += smem[threadIdx.x + off];
        __syncthreads();
    }

    // ---------- fused finalize: last block reduces all partials ----------
    __shared__ bool s_last;
    if (threadIdx.x == 0) {
        g_partials[b] = smem[0];
        __threadfence();
        unsigned int n = atomicAdd(&g_count, 1u);
        s_last = (n == (unsigned int)(N_BLOCKS - 1));
    }
    __syncthreads();
    if (s_last) {
        double* sd = reinterpret_cast<double*>(smem);
        if (threadIdx.x < 96) {
            double s = 0.0;
            #pragma unroll
            for (int q = 0; q < 3; ++q)          // 96 * 3 = 288, fixed order
                s += (double)g_partials[threadIdx.x * 3 + q];
            sd[threadIdx.x] = s;
        } else if (threadIdx.x < 128) {
            sd[threadIdx.x] = 0.0;
        }
        __syncthreads();
        #pragma unroll
        for (int off = 64; off > 0; off >>= 1) {
            if (threadIdx.x < off) sd[threadIdx.x] += sd[threadIdx.x + off];
            __syncthreads();
        }
        if (threadIdx.x == 0) {
            const double n = (double)N_PLANES * IMG_H * IMG_W;   // 23,592,960
            out[0] = (float)(1.0 - sd[0] / n);
            g_count = 0u;                         // reset for next graph replay
        }
    }
}

extern "C" void kernel_launch(void* const* d_in, const int* in_sizes, int n_in,
                              void* d_out, int out_size) {
    const float* pred = (const float*)d_in[0];
    const float* targ = (const float*)d_in[1];
    float* out = (float*)d_out;

    cudaFuncSetAttribute(ssim_main, cudaFuncAttributeMaxDynamicSharedMemorySize,
                         SMEM_BYTES);
    ssim_main<<<N_BLOCKS, NTHREADS, SMEM_BYTES>>>(pred, targ, out);
}

// round 14
// speedup vs baseline: 1.0005x; 1.0005x over previous
#include <cuda_runtime.h>
#include <cuda_bf16.h>

#define IMG_H 384
#define IMG_W 640
#define N_PLANES 96            // 32 * 3
#define WIN 11
#define HALO 5
#define OUT_W_TILE 246
#define NX 3                   // 246 + 246 + 148 = 640
#define NY 1
#define ROWS_PER_BLK (IMG_H / NY)       // 384
#define CHUNK 16
#define NCHUNKS (ROWS_PER_BLK / CHUNK)  // 24
#define NTHREADS 256

// SMEM layout (float units):
//   A01: CHUNK rows of VS2 float2 pairs (Sp, St)    -- packed
//   A23: CHUNK rows of VS1 floats      (Spp + Stt)
//   A4 : CHUNK rows of VS1 floats      (Spt)
// VS2=258: 2*VS2 = 516 == 4 (mod 32)  -> conflict-free 8-lane LDS.128 phases
// VS1=260: VS1 == 4 (mod 32)          -> conflict-free 8-lane LDS.128 phases
#define VS2 258
#define VS1 260
#define A01_OFF 0
#define A23_OFF (CHUNK * VS2 * 2)            // 8256
#define A4_OFF  (A23_OFF + CHUNK * VS1)      // 12416
#define SMEM_FLOATS (A4_OFF + CHUNK * VS1 + 64)  // 16640 (incl. overread pad)
#define SMEM_BYTES (SMEM_FLOATS * 4)             // 66560 B

#define C1F 1e-4f
#define C2F 9e-4f
#define N_BLOCKS (NX * NY * N_PLANES)  // 288

__device__ float g_partials[N_BLOCKS];
__device__ unsigned int g_count = 0;

// ---- packed f32x2 helpers (Blackwell FFMA2 path) ----
__device__ __forceinline__ unsigned long long pk2(float lo, float hi) {
    unsigned long long r;
    asm("mov.b64 %0, {%1, %2};" : "=l"(r) : "f"(lo), "f"(hi));
    return r;
}
__device__ __forceinline__ void upk2(unsigned long long v, float& lo, float& hi) {
    asm("mov.b64 {%0, %1}, %2;" : "=f"(lo), "=f"(hi) : "l"(v));
}
__device__ __forceinline__ unsigned long long add2(unsigned long long a, unsigned long long b) {
    unsigned long long r;
    asm("add.rn.f32x2 %0, %1, %2;" : "=l"(r) : "l"(a), "l"(b));
    return r;
}
__device__ __forceinline__ unsigned long long fma2(unsigned long long a, unsigned long long b,
                                                   unsigned long long c) {
    unsigned long long r;
    asm("fma.rn.f32x2 %0, %1, %2, %3;" : "=l"(r) : "l"(a), "l"(b), "l"(c));
    return r;
}
#define NEG1_X2 0xBF800000BF800000ULL   // packed (-1.0f, -1.0f)

__global__ __launch_bounds__(NTHREADS, 2)
void ssim_main(const float* __restrict__ pred, const float* __restrict__ targ,
               float* __restrict__ out) {
    extern __shared__ float smem[];

    const int b = blockIdx.x;
    const int xt = b % NX;
    const int plane = b / NX;

    const int x0 = xt * OUT_W_TILE;
    const int outw = min(OUT_W_TILE, IMG_W - x0);   // 246 or 148
    const int inw = outw + 2 * HALO;
    const int r0 = 0;

    const size_t poff = (size_t)plane * (IMG_H * IMG_W);
    const float* __restrict__ P = pred + poff;
    const float* __restrict__ T = targ + poff;

    // ---------- vertical-pass identity ----------
    const int c = threadIdx.x;               // buffer column
    const int gx = x0 - HALO + c;            // global column
    const bool cvalid = (c < inw);
    const bool colin = cvalid && (gx >= 0) && (gx < IMG_W);

    unsigned long long vs01 = 0ULL;          // packed (sum p, sum t)
    float vs23 = 0.f;                        // sum (p*p + t*t)
    float vs4 = 0.f;                         // sum (p*t)

    // 10-deep register shift-register of packed (p,t) input rows.
    unsigned long long hist[10];

    // warmup: rows -5 .. 4
    #pragma unroll
    for (int k = 0; k < 10; ++k) {
        const int rr = r0 - HALO + k;
        float p = 0.f, t = 0.f;
        if (colin && rr >= 0) {              // rr < IMG_H always in warmup
            p = P[rr * IMG_W + gx];
            t = T[rr * IMG_W + gx];
        }
        hist[k] = pk2(p, t);
        vs01 = add2(vs01, pk2(p, t));
        vs23 = fmaf(p, p, fmaf(t, t, vs23));
        vs4  = fmaf(p, t, vs4);
    }

    // ---------- horizontal-pass identity ----------
    const int hrow = threadIdx.x & (CHUNK - 1);   // 0..15
    const int hseg = threadIdx.x >> 4;            // 0..15
    const int xs = hseg * 16;
    const bool segvalid = (xs < outw);
    const int nvalid = segvalid ? min(16, outw - xs) : 0;

    float acc = 0.f;
    const float KK  = 1.0f / 121.0f;
    const float K2C = KK * KK;
    const float TK2 = 2.0f * K2C;
    const float C12 = C1F + C2F;

    for (int ch = 0; ch < NCHUNKS; ++ch) {
        const int rbase = r0 + ch * CHUNK;

        // ===== vertical pass: delta-form, 1 op/row on each carried chain =====
        #pragma unroll
        for (int i = 0; i < CHUNK; ++i) {
            // incoming row r+5
            const int rr = rbase + i + HALO;
            float p = 0.f, t = 0.f;
            if (colin && rr < IMG_H) {
                p = P[rr * IMG_W + gx];
                t = T[rr * IMG_W + gx];
            }
            const unsigned long long nw = pk2(p, t);
            float po, to; upk2(hist[0], po, to);

            // store values: old carried sum + incoming (off loop-carried chain)
            if (cvalid) {
                *reinterpret_cast<unsigned long long*>(
                    &smem[A01_OFF + (i * VS2 + c) * 2]) = add2(vs01, nw);
                smem[A23_OFF + i * VS1 + c] = fmaf(p, p, fmaf(t, t, vs23));
                smem[A4_OFF  + i * VS1 + c] = fmaf(p, t, vs4);
            }

            // carried updates: vs += (incoming - outgoing), deltas off-chain
            vs01 = add2(vs01, fma2(hist[0], NEG1_X2, nw));
            vs23 += fmaf(p, p, t * t) - fmaf(po, po, to * to);
            vs4  += fmaf(p, t, -(po * to));

            #pragma unroll
            for (int k = 0; k < 9; ++k) hist[k] = hist[k + 1];
            hist[9] = nw;
        }
        __syncthreads();

        // ===== horizontal pass: vectorized register-window sliding sums =====
        if (segvalid) {
            float numA[16], denF[16];

            // Pass A: packed (Sp, St) -> numA = 2k^2*ab + C1, denA = k^2*(a^2+b^2) + C1
            {
                const ulonglong2* b01 =
                    reinterpret_cast<const ulonglong2*>(smem) + ((hrow * VS2 + xs) >> 1);
                unsigned long long v[28];
                #pragma unroll
                for (int k = 0; k < 14; ++k) {
                    ulonglong2 u = b01[k];          // LDS.128, conflict-free
                    v[2 * k] = u.x; v[2 * k + 1] = u.y;
                }
                // tree sum of v[0..10]
                unsigned long long t01 = add2(v[0], v[1]);
                unsigned long long t23 = add2(v[2], v[3]);
                unsigned long long t45 = add2(v[4], v[5]);
                unsigned long long t67 = add2(v[6], v[7]);
                unsigned long long t89 = add2(v[8], v[9]);
                unsigned long long S = add2(add2(add2(t01, t23), add2(t45, t67)),
                                            add2(t89, v[10]));
                #pragma unroll
                for (int j = 0; j < 16; ++j) {
                    float a, bb; upk2(S, a, bb);
                    float ab = a * bb;
                    float V  = fmaf(a, a, bb * bb);
                    numA[j] = fmaf(TK2, ab, C1F);
                    denF[j] = fmaf(K2C, V, C1F);    // den1 (for now)
                    if (j < 15)                      // fused diff: 1 op on chain
                        S = add2(S, fma2(v[j], NEG1_X2, v[j + WIN]));
                }
            }
            // Pass B: S = box sum of (pp+tt); den2 = k*S - den1 + (C1+C2); denF = den1*den2
            {
                const float4* b23 =
                    reinterpret_cast<const float4*>(&smem[A23_OFF + hrow * VS1 + xs]);
                float w[28];
                #pragma unroll
                for (int k = 0; k < 7; ++k) {
                    float4 u = b23[k];
                    w[4*k] = u.x; w[4*k+1] = u.y; w[4*k+2] = u.z; w[4*k+3] = u.w;
                }
                float t01 = w[0] + w[1], t23 = w[2] + w[3];
                float t45 = w[4] + w[5], t67 = w[6] + w[7];
                float t89 = w[8] + w[9];
                float S = ((t01 + t23) + (t45 + t67)) + (t89 + w[10]);
                #pragma unroll
                for (int j = 0; j < 16; ++j) {
                    float den1 = denF[j];
                    float den2 = fmaf(KK, S, C12 - den1);
                    denF[j] = den1 * den2;
                    if (j < 15) {
                        float d = w[j + WIN] - w[j];   // off-chain diff
                        S += d;
                    }
                }
            }
            // Pass C: S = box sum of pt; num2 = 2k*S + C12 - n1;
            // quad fraction combining -> one divide per 4 pixels.
            {
                const float4* b4 =
                    reinterpret_cast<const float4*>(&smem[A4_OFF + hrow * VS1 + xs]);
                float w[28];
                #pragma unroll
                for (int k = 0; k < 7; ++k) {
                    float4 u = b4[k];
                    w[4*k] = u.x; w[4*k+1] = u.y; w[4*k+2] = u.z; w[4*k+3] = u.w;
                }
                float t01 = w[0] + w[1], t23 = w[2] + w[3];
                float t45 = w[4] + w[5], t67 = w[6] + w[7];
                float t89 = w[8] + w[9];
                float S = ((t01 + t23) + (t45 + t67)) + (t89 + w[10]);
                #pragma unroll
                for (int q = 0; q < 4; ++q) {
                    float Nacc, Dacc;
                    #pragma unroll
                    for (int u = 0; u < 4; ++u) {
                        const int j = q * 4 + u;
                        float n1 = numA[j];
                        float n2 = fmaf(2.0f * KK, S, C12 - n1);
                        float Nj = (j < nvalid) ? n1 * n2 : 0.f;
                        float Dj = (j < nvalid) ? denF[j] : 1.0f;
                        if (u == 0) { Nacc = Nj; Dacc = Dj; }
                        else {
                            Nacc = fmaf(Nacc, Dj, Nj * Dacc);
                            Dacc = Dacc * Dj;
                        }
                        if (j < 15) {
                            float d = w[j + WIN] - w[j];   // off-chain diff
                            S += d;
                        }
                    }
                    acc += __fdividef(Nacc, Dacc);
                }
            }
        }
        __syncthreads();
    }

    // ---------- deterministic block reduction ----------
    smem[threadIdx.x] = acc;
    __syncthreads();
    #pragma unroll
    for (int off = NTHREADS / 2; off > 0; off >>= 1) {
        if (threadIdx.x < off) smem[threadIdx.x] += smem[threadIdx.x + off];
        __syncthreads();
    }

    // ---------- fused finalize: last block reduces all partials ----------
    __shared__ bool s_last;
    if (threadIdx.x == 0) {
        g_partials[b] = smem[0];
        __threadfence();
        unsigned int n = atomicAdd(&g_count, 1u);
        s_last = (n == (unsigned int)(N_BLOCKS - 1));
    }
    __syncthreads();
    if (s_last) {
        double* sd = reinterpret_cast<double*>(smem);
        if (threadIdx.x < 96) {
            double s = 0.0;
            #pragma unroll
            for (int q = 0; q < 3; ++q)          // 96 * 3 = 288, fixed order
                s += (double)g_partials[threadIdx.x * 3 + q];
            sd[threadIdx.x] = s;
        } else if (threadIdx.x < 128) {
            sd[threadIdx.x] = 0.0;
        }
        __syncthreads();
        #pragma unroll
        for (int off = 64; off > 0; off >>= 1) {
            if (threadIdx.x < off) sd[threadIdx.x] += sd[threadIdx.x + off];
            __syncthreads();
        }
        if (threadIdx.x == 0) {
            const double n = (double)N_PLANES * IMG_H * IMG_W;   // 23,592,960
            out[0] = (float)(1.0 - sd[0] / n);
            g_count = 0u;                         // reset for next graph replay
        }
    }
}

extern "C" void kernel_launch(void* const* d_in, const int* in_sizes, int n_in,
                              void* d_out, int out_size) {
    const float* pred = (const float*)d_in[0];
    const float* targ = (const float*)d_in[1];
    float* out = (float*)d_out;

    cudaFuncSetAttribute(ssim_main, cudaFuncAttributeMaxDynamicSharedMemorySize,
                         SMEM_BYTES);
    ssim_main<<<N_BLOCKS, NTHREADS, SMEM_BYTES>>>(pred, targ, out);
}